// round 14
// baseline (speedup 1.0000x reference)
#include <cuda_runtime.h>
#include <math.h>
#include <stdint.h>

#define NB    8192      // batch
#define DK    768       // key dim
#define DIM   768       // embedding dim
#define POOL  30
#define PLEN  20
#define TOPK  5
#define HALF  10        // PLEN/2

// Scratch (no allocation allowed).
__device__ int g_idx[NB * TOPK];

// ---------------------------------------------------------------------------
// Kernel 1: fused norm + cosine-sim + top-5 (validated round 13, + PDL
// launch_dependents at the end so the gather grid can pre-dispatch).
// ---------------------------------------------------------------------------
__global__ __launch_bounds__(128) void topk_kernel(const float* __restrict__ xq,
                                                   const float* __restrict__ K) {
    int lane = threadIdx.x & 31;
    int wInB = threadIdx.x >> 5;                  // warp in block (0..3)
    int row0 = blockIdx.x * 16;
    int rBase = wInB * 4;                         // local rows rBase..rBase+3

    __shared__ float s_part[16][POOL][4];         // [localRow][k][residue] (dot partials)
    __shared__ float s_norm[POOL][4];             // [k][residue] (||K_k||^2 partials)

    const float4* q4 = reinterpret_cast<const float4*>(xq);
    float4 q[4][6];
#pragma unroll
    for (int r = 0; r < 4; r++) {
        const float4* src = q4 + (size_t)(row0 + rBase + r) * (DK / 4);
#pragma unroll
        for (int j = 0; j < 6; j++)
            q[r][j] = __ldg(src + j * 32 + lane);
    }

    const float4* K4 = reinterpret_cast<const float4*>(K);
    for (int k = 0; k < POOL; k++) {
        float a0 = 0.f, a1 = 0.f, a2 = 0.f, a3 = 0.f;
        float s  = 0.f;                           // dot(K_k, K_k)
        const float4* nk = K4 + k * (DK / 4);
#pragma unroll
        for (int j = 0; j < 6; j++) {
            float4 n = __ldg(nk + j * 32 + lane);
            a0 += q[0][j].x * n.x + q[0][j].y * n.y + q[0][j].z * n.z + q[0][j].w * n.w;
            a1 += q[1][j].x * n.x + q[1][j].y * n.y + q[1][j].z * n.z + q[1][j].w * n.w;
            a2 += q[2][j].x * n.x + q[2][j].y * n.y + q[2][j].z * n.z + q[2][j].w * n.w;
            a3 += q[3][j].x * n.x + q[3][j].y * n.y + q[3][j].z * n.z + q[3][j].w * n.w;
            s  += n.x * n.x + n.y * n.y + n.z * n.z + n.w * n.w;
        }
        // partial butterflies: 3 steps -> lane l (l<4) holds sum over lanes==l mod 4
#pragma unroll
        for (int off = 16; off >= 4; off >>= 1) {
            a0 += __shfl_xor_sync(0xFFFFFFFFu, a0, off);
            a1 += __shfl_xor_sync(0xFFFFFFFFu, a1, off);
            a2 += __shfl_xor_sync(0xFFFFFFFFu, a2, off);
            a3 += __shfl_xor_sync(0xFFFFFFFFu, a3, off);
            s  += __shfl_xor_sync(0xFFFFFFFFu, s,  off);
        }
        if (lane < 4) {
            s_part[rBase + 0][k][lane] = a0;
            s_part[rBase + 1][k][lane] = a1;
            s_part[rBase + 2][k][lane] = a2;
            s_part[rBase + 3][k][lane] = a3;
            if (wInB == 0) s_norm[k][lane] = s;   // all warps compute identical s
        }
    }
    __syncthreads();

    // ---------------- phase 3: finish reductions + serial top-5 -------------
    if (threadIdx.x < 16) {
        int lr  = threadIdx.x;
        int row = row0 + lr;
        float sims[POOL];
#pragma unroll
        for (int k = 0; k < POOL; k++) {
            float a = (s_part[lr][k][0] + s_part[lr][k][1])
                    + (s_part[lr][k][2] + s_part[lr][k][3]);
            float s = (s_norm[k][0] + s_norm[k][1])
                    + (s_norm[k][2] + s_norm[k][3]);
            sims[k] = a * (1.0f / sqrtf(fmaxf(s, 1e-24f)));  // = a / max(||K||,1e-12)
        }
        unsigned used = 0;
#pragma unroll
        for (int t = 0; t < TOPK; t++) {
            float best = -3.4e38f;
            int   bi   = 0;
#pragma unroll
            for (int k = 0; k < POOL; k++) {
                if ((used >> k) & 1u) continue;
                float v = sims[k];
                if (v > best) { best = v; bi = k; }   // strict > => smallest idx on ties
            }
            used |= (1u << bi);
            g_idx[row * TOPK + t] = bi;
        }
    }

    // All g_idx writes in this block are ordered before this point.
    __syncthreads();
    asm volatile("griddepcontrol.launch_dependents;" ::: "memory");
}

// ---------------------------------------------------------------------------
// Kernel 2: gather — branch-free. 192 threads so the half boundary (1920
// float4) divides exactly: two clean loops, no predication. __stcs streaming
// stores (validated). PDL wait before reading g_idx.
// ---------------------------------------------------------------------------
__global__ __launch_bounds__(192) void gather_kernel(const float* __restrict__ p,
                                                     float* __restrict__ out) {
    asm volatile("griddepcontrol.wait;" ::: "memory");

    int t = blockIdx.x;        // 0..4
    int b = blockIdx.y;        // 0..NB-1
    int k = g_idx[b * TOPK + t];

    const float4* src  = reinterpret_cast<const float4*>(p) + (size_t)k * (PLEN * DIM / 4);
    float4*       out4 = reinterpret_cast<float4*>(out);

    const size_t base0 = ((size_t)b * (TOPK * HALF) + (size_t)t * HALF) * (DIM / 4);
    const size_t base1 = ((size_t)(NB + b) * (TOPK * HALF) + (size_t)t * HALF) * (DIM / 4);
    const int    halfN = HALF * DIM / 4;   // 1920 float4 per half; 1920/192 = 10 iters

#pragma unroll 5
    for (int j = 0; j < 10; j++) {
        int i = threadIdx.x + j * 192;
        __stcs(out4 + base0 + i, __ldg(src + i));
    }
#pragma unroll 5
    for (int j = 0; j < 10; j++) {
        int i = threadIdx.x + j * 192;
        __stcs(out4 + base1 + i, __ldg(src + halfN + i));
    }
}

// ---------------------------------------------------------------------------
extern "C" void kernel_launch(void* const* d_in, const int* in_sizes, int n_in,
                              void* d_out, int out_size) {
    const float* xq = (const float*)d_in[0];   // x_query [8192,768]
    // d_in[1] = x (unused)
    const float* K  = (const float*)d_in[2];   // [30,768]
    const float* p  = (const float*)d_in[3];   // [30,20,768]
    float*       out = (float*)d_out;          // [2,8192,50,768]

    topk_kernel<<<NB / 16, 128>>>(xq, K);

    // Gather with programmatic dependent launch: dispatch overlaps topk tail;
    // griddepcontrol.wait inside orders the g_idx read.
    cudaLaunchConfig_t cfg = {};
    cfg.gridDim  = dim3(TOPK, NB);
    cfg.blockDim = dim3(192);
    cudaLaunchAttribute at[1];
    at[0].id = cudaLaunchAttributeProgrammaticStreamSerialization;
    at[0].val.programmaticStreamSerializationAllowed = 1;
    cfg.attrs = at;
    cfg.numAttrs = 1;
    cudaLaunchKernelEx(&cfg, gather_kernel, p, (float*)d_out);
}